// round 4
// baseline (speedup 1.0000x reference)
#include <cuda_runtime.h>
#include <cuda_bf16.h>
#include <mma.h>
#include <cstdint>
#include <math.h>

using namespace nvcuda;

// Problem constants
#define BB   4
#define TT   2048
#define CC   1024
#define NQ   8
#define DD   128
#define MM   (BB*TT)          // 8192 rows
#define NQKV (DD*(NQ+2))      // 1280

// ---------------- scratch (no allocations allowed) ----------------
__device__ float g_Wcat[NQKV * CC];     // [1280][1024] K-major (transposed, tf32-rounded)
__device__ float g_WpT [CC * CC];       // [1024][1024] K-major (transposed, tf32-rounded)
__device__ float g_qkv [MM * NQKV];     // [8192][1280]  k|v|q per token
__device__ float g_attn[MM * CC];       // [8192][1024]  attention output (B,T,NQ,D)

__device__ __forceinline__ float to_tf32(float x) {
    float r;
    asm("cvt.rna.tf32.f32 %0, %1;" : "=f"(r) : "f"(x));
    return r;
}

// ---------------- weight transposes (to K-major [N][K], tf32-rounded) ----------------
__global__ void pack_qkv_t_kernel(const float* __restrict__ Wk,
                                  const float* __restrict__ Wv,
                                  const float* __restrict__ Wq,
                                  float* __restrict__ out) {
    __shared__ float t[32][33];
    int c0 = blockIdx.x * 32;
    int n0 = blockIdx.y * 32;
    int tx = threadIdx.x, ty = threadIdx.y;
#pragma unroll
    for (int p = 0; p < 4; p++) {
        int c = c0 + ty + p * 8;
        int n = n0 + tx;
        float v;
        if (n < DD)            v = Wk[c * DD + n];
        else if (n < 2 * DD)   v = Wv[c * DD + (n - DD)];
        else {
            int h = (n - 2 * DD) >> 7;
            int d = (n - 2 * DD) & 127;
            v = Wq[((size_t)h * CC + c) * DD + d];
        }
        t[ty + p * 8][tx] = to_tf32(v);
    }
    __syncthreads();
#pragma unroll
    for (int p = 0; p < 4; p++)
        out[(size_t)(n0 + ty + p * 8) * CC + c0 + tx] = t[tx][ty + p * 8];
}

__global__ void pack_wp_t_kernel(const float* __restrict__ Wp, float* __restrict__ out) {
    __shared__ float t[32][33];
    int c0 = blockIdx.x * 32;
    int n0 = blockIdx.y * 32;
    int tx = threadIdx.x, ty = threadIdx.y;
#pragma unroll
    for (int p = 0; p < 4; p++)
        t[ty + p * 8][tx] = to_tf32(Wp[(size_t)(c0 + ty + p * 8) * CC + n0 + tx]);
    __syncthreads();
#pragma unroll
    for (int p = 0; p < 4; p++)
        out[(size_t)(n0 + ty + p * 8) * CC + c0 + tx] = t[tx][ty + p * 8];
}

// ---------------- wmma tf32 GEMM: C[M,N] = A[M,K] @ Bt[N,K]^T (+bias) ----------------
#define GPAD 20   // smem row pitch (floats)

__global__ __launch_bounds__(256, 2)
void wmma_gemm(const float* __restrict__ A, const float* __restrict__ Bt,
               const float* __restrict__ bias, float* __restrict__ C,
               int M, int N, int K) {
    __shared__ float As[2][128][GPAD];
    __shared__ float Bs[2][128][GPAD];

    const int tid  = threadIdx.x;
    const int warp = tid >> 5;
    const int lane = tid & 31;
    const int wm   = warp >> 1;
    const int wn   = warp & 1;
    const int m0 = blockIdx.y * 128;
    const int n0 = blockIdx.x * 128;

    const float* Ab = A  + (size_t)m0 * K;
    const float* Bb = Bt + (size_t)n0 * K;

    wmma::fragment<wmma::accumulator, 16, 16, 8, float> acc[2][4];
#pragma unroll
    for (int i = 0; i < 2; i++)
#pragma unroll
        for (int j = 0; j < 4; j++)
            wmma::fill_fragment(acc[i][j], 0.0f);

    const int lr = tid >> 1;
    const int lc = (tid & 1) * 8;
    const int nk = K / 16;

    {
        const float* ap = Ab + (size_t)lr * K + lc;
        const float* bp = Bb + (size_t)lr * K + lc;
        float4 a0 = *reinterpret_cast<const float4*>(ap);
        float4 a1 = *reinterpret_cast<const float4*>(ap + 4);
        float4 b0 = *reinterpret_cast<const float4*>(bp);
        float4 b1 = *reinterpret_cast<const float4*>(bp + 4);
        a0.x=to_tf32(a0.x); a0.y=to_tf32(a0.y); a0.z=to_tf32(a0.z); a0.w=to_tf32(a0.w);
        a1.x=to_tf32(a1.x); a1.y=to_tf32(a1.y); a1.z=to_tf32(a1.z); a1.w=to_tf32(a1.w);
        *reinterpret_cast<float4*>(&As[0][lr][lc])     = a0;
        *reinterpret_cast<float4*>(&As[0][lr][lc + 4]) = a1;
        *reinterpret_cast<float4*>(&Bs[0][lr][lc])     = b0;
        *reinterpret_cast<float4*>(&Bs[0][lr][lc + 4]) = b1;
    }
    __syncthreads();

    int buf = 0;
    for (int c = 0; c < nk; c++) {
        float4 ra0, ra1, rb0, rb1;
        const bool pf = (c + 1 < nk);
        if (pf) {
            const float* ap = Ab + (size_t)lr * K + (c + 1) * 16 + lc;
            const float* bp = Bb + (size_t)lr * K + (c + 1) * 16 + lc;
            ra0 = *reinterpret_cast<const float4*>(ap);
            ra1 = *reinterpret_cast<const float4*>(ap + 4);
            rb0 = *reinterpret_cast<const float4*>(bp);
            rb1 = *reinterpret_cast<const float4*>(bp + 4);
        }

#pragma unroll
        for (int ks = 0; ks < 2; ks++) {
            wmma::fragment<wmma::matrix_a, 16, 16, 8, wmma::precision::tf32, wmma::row_major> af[2];
            wmma::fragment<wmma::matrix_b, 16, 16, 8, wmma::precision::tf32, wmma::col_major> bf[4];
#pragma unroll
            for (int i = 0; i < 2; i++)
                wmma::load_matrix_sync(af[i], &As[buf][wm * 32 + i * 16][ks * 8], GPAD);
#pragma unroll
            for (int j = 0; j < 4; j++)
                wmma::load_matrix_sync(bf[j], &Bs[buf][wn * 64 + j * 16][ks * 8], GPAD);
#pragma unroll
            for (int i = 0; i < 2; i++)
#pragma unroll
                for (int j = 0; j < 4; j++)
                    wmma::mma_sync(acc[i][j], af[i], bf[j], acc[i][j]);
        }

        if (pf) {
            int nb = buf ^ 1;
            ra0.x=to_tf32(ra0.x); ra0.y=to_tf32(ra0.y); ra0.z=to_tf32(ra0.z); ra0.w=to_tf32(ra0.w);
            ra1.x=to_tf32(ra1.x); ra1.y=to_tf32(ra1.y); ra1.z=to_tf32(ra1.z); ra1.w=to_tf32(ra1.w);
            *reinterpret_cast<float4*>(&As[nb][lr][lc])     = ra0;
            *reinterpret_cast<float4*>(&As[nb][lr][lc + 4]) = ra1;
            *reinterpret_cast<float4*>(&Bs[nb][lr][lc])     = rb0;
            *reinterpret_cast<float4*>(&Bs[nb][lr][lc + 4]) = rb1;
        }
        __syncthreads();
        buf ^= 1;
    }

    float* stage = &As[0][0][0] + warp * 320;
    const int er = lane >> 1;
    const int ec = (lane & 1) * 8;
#pragma unroll
    for (int i = 0; i < 2; i++) {
#pragma unroll
        for (int j = 0; j < 4; j++) {
            wmma::store_matrix_sync(stage, acc[i][j], GPAD, wmma::mem_row_major);
            __syncwarp();
            int gm = m0 + wm * 32 + i * 16 + er;
            int gn = n0 + wn * 64 + j * 16 + ec;
            float4 v0 = *reinterpret_cast<const float4*>(stage + er * GPAD + ec);
            float4 v1 = *reinterpret_cast<const float4*>(stage + er * GPAD + ec + 4);
            if (bias) {
                v0.x += bias[gn];     v0.y += bias[gn + 1];
                v0.z += bias[gn + 2]; v0.w += bias[gn + 3];
                v1.x += bias[gn + 4]; v1.y += bias[gn + 5];
                v1.z += bias[gn + 6]; v1.w += bias[gn + 7];
            }
            *reinterpret_cast<float4*>(C + (size_t)gm * N + gn)     = v0;
            *reinterpret_cast<float4*>(C + (size_t)gm * N + gn + 4) = v1;
            __syncwarp();
        }
    }
}

// ---------------- causal MQA flash attention, wmma tf32 ----------------
// 64 q-rows x 64 k-cols per iter, D=128. 128 threads / 4 warps; warp w owns
// q-rows [w*16, w*16+16). S and PV on tensor cores; softmax + O-rescale scalar.
#define APITCH 132
#define SPITCH 68
#define ASMEM  ((4 * 64 * APITCH + 64 * SPITCH) * 4)

__global__ __launch_bounds__(128, 1)
void mqa_wmma_kernel(const float* __restrict__ qkv, float* __restrict__ out) {
    extern __shared__ float smf[];
    float* Qs = smf;                   // [64][APITCH]
    float* Ks = Qs + 64 * APITCH;      // [64][APITCH] (natural [s][d] = col_major B)
    float* Vs = Ks + 64 * APITCH;      // [64][APITCH] (natural [s][d] = row_major B)
    float* Os = Vs + 64 * APITCH;      // [64][APITCH] fp32 accum
    float* Ps = Os + 64 * APITCH;      // [64][SPITCH] scores / probabilities

    const int tid  = threadIdx.x;
    const int warp = tid >> 5;
    const int lane = tid & 31;
    const int qt = gridDim.x - 1 - blockIdx.x;   // heavy tiles first
    const int h  = blockIdx.y;
    const int b  = blockIdx.z;
    const int q0 = qt * 64;
    const float scale = 1.0f / 32.0f;            // C^-0.5

    const float* kbase = qkv + (size_t)(b * TT) * NQKV;
    const float* vbase = kbase + DD;
    const float* qbase = kbase + 2 * DD + h * DD;

    // Q tile (scaled + tf32) and O zero
    for (int l = tid; l < 64 * 32; l += 128) {
        int r  = l >> 5;
        int dv = l & 31;
        float4 v = *reinterpret_cast<const float4*>(qbase + (size_t)(q0 + r) * NQKV + dv * 4);
        v.x = to_tf32(v.x * scale); v.y = to_tf32(v.y * scale);
        v.z = to_tf32(v.z * scale); v.w = to_tf32(v.w * scale);
        *reinterpret_cast<float4*>(&Qs[r * APITCH + dv * 4]) = v;
        *reinterpret_cast<float4*>(&Os[r * APITCH + dv * 4]) = make_float4(0.f, 0.f, 0.f, 0.f);
    }

    // per-lane row state: row = warp*16 + (lane>>1); duplicated across lane pairs
    const int rloc = lane >> 1;              // 0..15
    const int half = lane & 1;               // 0 or 1 (32-col half)
    const int grow = q0 + warp * 16 + rloc;  // global query row
    float mrow = -1e30f, lrow = 0.f;

    const int rowbase = warp * 16;
    const int nkb = qt + 1;

    for (int kb = 0; kb < nkb; kb++) {
        const int s0 = kb * 64;
        __syncthreads();   // protect Ks/Vs from previous iteration (and publish Qs/Os on iter 0)

        for (int l = tid; l < 64 * 32; l += 128) {
            int s  = l >> 5;
            int dv = l & 31;
            float4 kv = *reinterpret_cast<const float4*>(kbase + (size_t)(s0 + s) * NQKV + dv * 4);
            kv.x = to_tf32(kv.x); kv.y = to_tf32(kv.y); kv.z = to_tf32(kv.z); kv.w = to_tf32(kv.w);
            *reinterpret_cast<float4*>(&Ks[s * APITCH + dv * 4]) = kv;
            float4 vv = *reinterpret_cast<const float4*>(vbase + (size_t)(s0 + s) * NQKV + dv * 4);
            vv.x = to_tf32(vv.x); vv.y = to_tf32(vv.y); vv.z = to_tf32(vv.z); vv.w = to_tf32(vv.w);
            *reinterpret_cast<float4*>(&Vs[s * APITCH + dv * 4]) = vv;
        }
        __syncthreads();

        // ---- S = Q @ K^T (warp: 16x64) ----
        {
            wmma::fragment<wmma::accumulator, 16, 16, 8, float> sa[4];
#pragma unroll
            for (int j = 0; j < 4; j++) wmma::fill_fragment(sa[j], 0.0f);
#pragma unroll
            for (int k = 0; k < 16; k++) {
                wmma::fragment<wmma::matrix_a, 16, 16, 8, wmma::precision::tf32, wmma::row_major> af;
                wmma::load_matrix_sync(af, &Qs[rowbase * APITCH + k * 8], APITCH);
#pragma unroll
                for (int j = 0; j < 4; j++) {
                    wmma::fragment<wmma::matrix_b, 16, 16, 8, wmma::precision::tf32, wmma::col_major> bf;
                    wmma::load_matrix_sync(bf, &Ks[(j * 16) * APITCH + k * 8], APITCH);
                    wmma::mma_sync(sa[j], af, bf, sa[j]);
                }
            }
#pragma unroll
            for (int j = 0; j < 4; j++)
                wmma::store_matrix_sync(&Ps[rowbase * SPITCH + j * 16], sa[j], SPITCH, wmma::mem_row_major);
        }
        __syncwarp();

        // ---- online softmax on my row half (32 cols) ----
        {
            float* srow = &Ps[(rowbase + rloc) * SPITCH + half * 32];
            // lim = last valid local col index within this half (causal)
            int lim = 63;
            if (kb == nkb - 1) lim = grow - s0 - half * 32;   // may be <0 (all masked)
            float mloc = -1e30f;
#pragma unroll
            for (int j = 0; j < 32; j++) {
                float s = (j <= lim) ? srow[j] : -1e30f;
                mloc = fmaxf(mloc, s);
            }
            mloc = fmaxf(mloc, __shfl_xor_sync(0xffffffffu, mloc, 1));
            float mnew = fmaxf(mrow, mloc);
            float corr = __expf(mrow - mnew);
            mrow = mnew;
            float lloc = 0.f;
#pragma unroll
            for (int j = 0; j < 32; j++) {
                float p = (j <= lim) ? __expf(srow[j] - mnew) : 0.f;
                srow[j] = p;
                lloc += p;
            }
            lloc += __shfl_xor_sync(0xffffffffu, lloc, 1);
            lrow = lrow * corr + lloc;

            // rescale my O row half (64 cols)
            if (corr != 1.0f) {
                float* orow = &Os[(rowbase + rloc) * APITCH + half * 64];
#pragma unroll
                for (int j = 0; j < 16; j++) {
                    float4 v = *reinterpret_cast<float4*>(orow + j * 4);
                    v.x *= corr; v.y *= corr; v.z *= corr; v.w *= corr;
                    *reinterpret_cast<float4*>(orow + j * 4) = v;
                }
            }
        }
        __syncwarp();

        // ---- O += P @ V (warp: 16x128, two 64-wide halves) ----
#pragma unroll
        for (int nh = 0; nh < 2; nh++) {
            wmma::fragment<wmma::accumulator, 16, 16, 8, float> oa[4];
#pragma unroll
            for (int j = 0; j < 4; j++)
                wmma::load_matrix_sync(oa[j], &Os[rowbase * APITCH + nh * 64 + j * 16], APITCH, wmma::mem_row_major);
#pragma unroll
            for (int k = 0; k < 8; k++) {
                wmma::fragment<wmma::matrix_a, 16, 16, 8, wmma::precision::tf32, wmma::row_major> af;
                wmma::load_matrix_sync(af, &Ps[rowbase * SPITCH + k * 8], SPITCH);
#pragma unroll
                for (int j = 0; j < 4; j++) {
                    wmma::fragment<wmma::matrix_b, 16, 16, 8, wmma::precision::tf32, wmma::row_major> bf;
                    wmma::load_matrix_sync(bf, &Vs[(k * 8) * APITCH + nh * 64 + j * 16], APITCH);
                    wmma::mma_sync(oa[j], af, bf, oa[j]);
                }
            }
#pragma unroll
            for (int j = 0; j < 4; j++)
                wmma::store_matrix_sync(&Os[rowbase * APITCH + nh * 64 + j * 16], oa[j], APITCH, wmma::mem_row_major);
        }
        __syncwarp();
    }

    // epilogue: normalize my row half and write [B,T,NQ,D]
    {
        float rl = 1.0f / lrow;
        const float* orow = &Os[(rowbase + rloc) * APITCH + half * 64];
        float* op = out + ((size_t)(b * TT + grow) * NQ + h) * DD + half * 64;
#pragma unroll
        for (int j = 0; j < 16; j++) {
            float4 v = *reinterpret_cast<const float4*>(orow + j * 4);
            v.x *= rl; v.y *= rl; v.z *= rl; v.w *= rl;
            *reinterpret_cast<float4*>(op + j * 4) = v;
        }
    }
}

// ---------------- launch ----------------
extern "C" void kernel_launch(void* const* d_in, const int* in_sizes, int n_in,
                              void* d_out, int out_size) {
    const float* x  = (const float*)d_in[0];
    const float* Wk = (const float*)d_in[1];
    const float* Wv = (const float*)d_in[2];
    const float* Wq = (const float*)d_in[3];
    const float* Wp = (const float*)d_in[4];
    const float* bp = (const float*)d_in[5];
    float* out = (float*)d_out;

    float *wcat, *wpT, *qkv, *attn;
    cudaGetSymbolAddress((void**)&wcat, g_Wcat);
    cudaGetSymbolAddress((void**)&wpT,  g_WpT);
    cudaGetSymbolAddress((void**)&qkv,  g_qkv);
    cudaGetSymbolAddress((void**)&attn, g_attn);

    cudaFuncSetAttribute(mqa_wmma_kernel, cudaFuncAttributeMaxDynamicSharedMemorySize, ASMEM);

    // 1) transpose+pack weights to K-major (tf32-rounded)
    pack_qkv_t_kernel<<<dim3(CC / 32, NQKV / 32), dim3(32, 8)>>>(Wk, Wv, Wq, wcat);
    pack_wp_t_kernel<<<dim3(CC / 32, CC / 32), dim3(32, 8)>>>(Wp, wpT);

    // 2) fused QKV projection (wmma tf32)
    wmma_gemm<<<dim3(NQKV / 128, MM / 128), 256>>>(x, wcat, nullptr, qkv, MM, NQKV, CC);

    // 3) causal MQA attention (wmma tf32) -> [B,T,NQ,D]
    mqa_wmma_kernel<<<dim3(TT / 64, NQ, BB), 128, ASMEM>>>(qkv, attn);

    // 4) output projection (wmma tf32) + bias
    wmma_gemm<<<dim3(CC / 128, MM / 128), 256>>>(attn, wpT, bp, out, MM, CC, CC);
}

// round 5
// speedup vs baseline: 2.7747x; 2.7747x over previous
#include <cuda_runtime.h>
#include <cuda_bf16.h>
#include <mma.h>
#include <cstdint>
#include <math.h>

using namespace nvcuda;

// Problem constants
#define BB   4
#define TT   2048
#define CC   1024
#define NQ   8
#define DD   128
#define MM   (BB*TT)          // 8192 rows
#define NQKV (DD*(NQ+2))      // 1280

// ---------------- scratch (no allocations allowed) ----------------
__device__ float g_Wcat[NQKV * CC];     // [1280][1024] K-major (transposed, tf32-rounded)
__device__ float g_WpT [CC * CC];       // [1024][1024] K-major (transposed, tf32-rounded)
__device__ float g_qkv [MM * NQKV];     // [8192][1280]  k|v|q per token
__device__ float g_attn[MM * CC];       // [8192][1024]  attention output (B,T,NQ,D)

__device__ __forceinline__ float to_tf32(float x) {
    float r;
    asm("cvt.rna.tf32.f32 %0, %1;" : "=f"(r) : "f"(x));
    return r;
}

// mma.sync m16n8k8 tf32: C[16x8] += A[16x8] * B[8x8]
// A frag: a0=(g, t4) a1=(g+8, t4) a2=(g, t4+4) a3=(g+8, t4+4)
// B frag: b0=(k=t4, n=g) b1=(k=t4+4, n=g)
// C frag: c0=(g, 2t4) c1=(g, 2t4+1) c2=(g+8, 2t4) c3=(g+8, 2t4+1)
__device__ __forceinline__ void mma_tf32(float c[4], const uint32_t a[4], const uint32_t b[2]) {
    asm volatile(
        "mma.sync.aligned.m16n8k8.row.col.f32.tf32.tf32.f32 "
        "{%0,%1,%2,%3}, {%4,%5,%6,%7}, {%8,%9}, {%0,%1,%2,%3};"
        : "+f"(c[0]), "+f"(c[1]), "+f"(c[2]), "+f"(c[3])
        : "r"(a[0]), "r"(a[1]), "r"(a[2]), "r"(a[3]), "r"(b[0]), "r"(b[1]));
}

// ---------------- weight transposes (to K-major [N][K], tf32-rounded) ----------------
__global__ void pack_qkv_t_kernel(const float* __restrict__ Wk,
                                  const float* __restrict__ Wv,
                                  const float* __restrict__ Wq,
                                  float* __restrict__ out) {
    __shared__ float t[32][33];
    int c0 = blockIdx.x * 32;
    int n0 = blockIdx.y * 32;
    int tx = threadIdx.x, ty = threadIdx.y;
#pragma unroll
    for (int p = 0; p < 4; p++) {
        int c = c0 + ty + p * 8;
        int n = n0 + tx;
        float v;
        if (n < DD)            v = Wk[c * DD + n];
        else if (n < 2 * DD)   v = Wv[c * DD + (n - DD)];
        else {
            int h = (n - 2 * DD) >> 7;
            int d = (n - 2 * DD) & 127;
            v = Wq[((size_t)h * CC + c) * DD + d];
        }
        t[ty + p * 8][tx] = to_tf32(v);
    }
    __syncthreads();
#pragma unroll
    for (int p = 0; p < 4; p++)
        out[(size_t)(n0 + ty + p * 8) * CC + c0 + tx] = t[tx][ty + p * 8];
}

__global__ void pack_wp_t_kernel(const float* __restrict__ Wp, float* __restrict__ out) {
    __shared__ float t[32][33];
    int c0 = blockIdx.x * 32;
    int n0 = blockIdx.y * 32;
    int tx = threadIdx.x, ty = threadIdx.y;
#pragma unroll
    for (int p = 0; p < 4; p++)
        t[ty + p * 8][tx] = to_tf32(Wp[(size_t)(c0 + ty + p * 8) * CC + n0 + tx]);
    __syncthreads();
#pragma unroll
    for (int p = 0; p < 4; p++)
        out[(size_t)(n0 + ty + p * 8) * CC + c0 + tx] = t[tx][ty + p * 8];
}

// ---------------- wmma tf32 GEMM (unchanged, validated) ----------------
#define GPAD 20

__global__ __launch_bounds__(256, 2)
void wmma_gemm(const float* __restrict__ A, const float* __restrict__ Bt,
               const float* __restrict__ bias, float* __restrict__ C,
               int M, int N, int K) {
    __shared__ float As[2][128][GPAD];
    __shared__ float Bs[2][128][GPAD];

    const int tid  = threadIdx.x;
    const int warp = tid >> 5;
    const int lane = tid & 31;
    const int wm   = warp >> 1;
    const int wn   = warp & 1;
    const int m0 = blockIdx.y * 128;
    const int n0 = blockIdx.x * 128;

    const float* Ab = A  + (size_t)m0 * K;
    const float* Bb = Bt + (size_t)n0 * K;

    wmma::fragment<wmma::accumulator, 16, 16, 8, float> acc[2][4];
#pragma unroll
    for (int i = 0; i < 2; i++)
#pragma unroll
        for (int j = 0; j < 4; j++)
            wmma::fill_fragment(acc[i][j], 0.0f);

    const int lr = tid >> 1;
    const int lc = (tid & 1) * 8;
    const int nk = K / 16;

    {
        const float* ap = Ab + (size_t)lr * K + lc;
        const float* bp = Bb + (size_t)lr * K + lc;
        float4 a0 = *reinterpret_cast<const float4*>(ap);
        float4 a1 = *reinterpret_cast<const float4*>(ap + 4);
        float4 b0 = *reinterpret_cast<const float4*>(bp);
        float4 b1 = *reinterpret_cast<const float4*>(bp + 4);
        a0.x=to_tf32(a0.x); a0.y=to_tf32(a0.y); a0.z=to_tf32(a0.z); a0.w=to_tf32(a0.w);
        a1.x=to_tf32(a1.x); a1.y=to_tf32(a1.y); a1.z=to_tf32(a1.z); a1.w=to_tf32(a1.w);
        *reinterpret_cast<float4*>(&As[0][lr][lc])     = a0;
        *reinterpret_cast<float4*>(&As[0][lr][lc + 4]) = a1;
        *reinterpret_cast<float4*>(&Bs[0][lr][lc])     = b0;
        *reinterpret_cast<float4*>(&Bs[0][lr][lc + 4]) = b1;
    }
    __syncthreads();

    int buf = 0;
    for (int c = 0; c < nk; c++) {
        float4 ra0, ra1, rb0, rb1;
        const bool pf = (c + 1 < nk);
        if (pf) {
            const float* ap = Ab + (size_t)lr * K + (c + 1) * 16 + lc;
            const float* bp = Bb + (size_t)lr * K + (c + 1) * 16 + lc;
            ra0 = *reinterpret_cast<const float4*>(ap);
            ra1 = *reinterpret_cast<const float4*>(ap + 4);
            rb0 = *reinterpret_cast<const float4*>(bp);
            rb1 = *reinterpret_cast<const float4*>(bp + 4);
        }

#pragma unroll
        for (int ks = 0; ks < 2; ks++) {
            wmma::fragment<wmma::matrix_a, 16, 16, 8, wmma::precision::tf32, wmma::row_major> af[2];
            wmma::fragment<wmma::matrix_b, 16, 16, 8, wmma::precision::tf32, wmma::col_major> bf[4];
#pragma unroll
            for (int i = 0; i < 2; i++)
                wmma::load_matrix_sync(af[i], &As[buf][wm * 32 + i * 16][ks * 8], GPAD);
#pragma unroll
            for (int j = 0; j < 4; j++)
                wmma::load_matrix_sync(bf[j], &Bs[buf][wn * 64 + j * 16][ks * 8], GPAD);
#pragma unroll
            for (int i = 0; i < 2; i++)
#pragma unroll
                for (int j = 0; j < 4; j++)
                    wmma::mma_sync(acc[i][j], af[i], bf[j], acc[i][j]);
        }

        if (pf) {
            int nb = buf ^ 1;
            ra0.x=to_tf32(ra0.x); ra0.y=to_tf32(ra0.y); ra0.z=to_tf32(ra0.z); ra0.w=to_tf32(ra0.w);
            ra1.x=to_tf32(ra1.x); ra1.y=to_tf32(ra1.y); ra1.z=to_tf32(ra1.z); ra1.w=to_tf32(ra1.w);
            *reinterpret_cast<float4*>(&As[nb][lr][lc])     = ra0;
            *reinterpret_cast<float4*>(&As[nb][lr][lc + 4]) = ra1;
            *reinterpret_cast<float4*>(&Bs[nb][lr][lc])     = rb0;
            *reinterpret_cast<float4*>(&Bs[nb][lr][lc + 4]) = rb1;
        }
        __syncthreads();
        buf ^= 1;
    }

    float* stage = &As[0][0][0] + warp * 320;
    const int er = lane >> 1;
    const int ec = (lane & 1) * 8;
#pragma unroll
    for (int i = 0; i < 2; i++) {
#pragma unroll
        for (int j = 0; j < 4; j++) {
            wmma::store_matrix_sync(stage, acc[i][j], GPAD, wmma::mem_row_major);
            __syncwarp();
            int gm = m0 + wm * 32 + i * 16 + er;
            int gn = n0 + wn * 64 + j * 16 + ec;
            float4 v0 = *reinterpret_cast<const float4*>(stage + er * GPAD + ec);
            float4 v1 = *reinterpret_cast<const float4*>(stage + er * GPAD + ec + 4);
            if (bias) {
                v0.x += bias[gn];     v0.y += bias[gn + 1];
                v0.z += bias[gn + 2]; v0.w += bias[gn + 3];
                v1.x += bias[gn + 4]; v1.y += bias[gn + 5];
                v1.z += bias[gn + 6]; v1.w += bias[gn + 7];
            }
            *reinterpret_cast<float4*>(C + (size_t)gm * N + gn)     = v0;
            *reinterpret_cast<float4*>(C + (size_t)gm * N + gn + 4) = v1;
            __syncwarp();
        }
    }
}

// ---------------- causal MQA flash attention, mma.sync tf32, register-resident ----------------
// 64 q-rows/CTA, 4 warps x 16 rows; key blocks of 64. O/S/Q fragments in registers.
#define KPITCH 132
#define VPITCH 136
#define PPITCH 68
#define FASMEM ((64*KPITCH + 64*KPITCH + 64*VPITCH) * 4)   // Qs(->Ps) + Ks + Vs

__global__ __launch_bounds__(128, 2)
void mqa_fa_kernel(const float* __restrict__ qkv, float* __restrict__ out) {
    extern __shared__ float smf[];
    float* Qs = smf;                   // [64][KPITCH]; reused as Ps[64][PPITCH] after Q->regs
    float* Ks = Qs + 64 * KPITCH;      // [64][KPITCH]
    float* Vs = Ks + 64 * KPITCH;      // [64][VPITCH]
    float* Ps = Qs;

    const int tid  = threadIdx.x;
    const int warp = tid >> 5;
    const int lane = tid & 31;
    const int g    = lane >> 2;        // 0..7
    const int t4   = lane & 3;         // 0..3
    const int qt = gridDim.x - 1 - blockIdx.x;   // heavy tiles first
    const int h  = blockIdx.y;
    const int b  = blockIdx.z;
    const int q0 = qt * 64;
    const float scale = 1.0f / 32.0f;  // C^-0.5

    const float* kbase = qkv + (size_t)(b * TT) * NQKV;
    const float* vbase = kbase + DD;
    const float* qbase = kbase + 2 * DD + h * DD;

    // Q tile -> smem (scaled + tf32)
    for (int l = tid; l < 64 * 32; l += 128) {
        int r  = l >> 5;
        int dv = l & 31;
        float4 v = *reinterpret_cast<const float4*>(qbase + (size_t)(q0 + r) * NQKV + dv * 4);
        v.x = to_tf32(v.x * scale); v.y = to_tf32(v.y * scale);
        v.z = to_tf32(v.z * scale); v.w = to_tf32(v.w * scale);
        *reinterpret_cast<float4*>(&Qs[r * KPITCH + dv * 4]) = v;
    }
    __syncthreads();

    // Q fragments -> registers (16 k-steps)
    const int r0 = warp * 16 + g;
    const int r1 = r0 + 8;
    uint32_t qf[16][4];
#pragma unroll
    for (int s = 0; s < 16; s++) {
        qf[s][0] = __float_as_uint(Qs[r0 * KPITCH + s * 8 + t4]);
        qf[s][1] = __float_as_uint(Qs[r1 * KPITCH + s * 8 + t4]);
        qf[s][2] = __float_as_uint(Qs[r0 * KPITCH + s * 8 + t4 + 4]);
        qf[s][3] = __float_as_uint(Qs[r1 * KPITCH + s * 8 + t4 + 4]);
    }

    float o[16][4];
#pragma unroll
    for (int n = 0; n < 16; n++) { o[n][0]=0.f; o[n][1]=0.f; o[n][2]=0.f; o[n][3]=0.f; }
    float m0r = -1e30f, m1r = -1e30f, l0r = 0.f, l1r = 0.f;

    const int nkb = qt + 1;
    for (int kb = 0; kb < nkb; kb++) {
        const int s0 = kb * 64;
        __syncthreads();   // Ks/Vs/Ps free (all warps done with previous block; Q regs loaded)

        for (int l = tid; l < 64 * 32; l += 128) {
            int r  = l >> 5;
            int dv = l & 31;
            float4 kv = *reinterpret_cast<const float4*>(kbase + (size_t)(s0 + r) * NQKV + dv * 4);
            kv.x = to_tf32(kv.x); kv.y = to_tf32(kv.y); kv.z = to_tf32(kv.z); kv.w = to_tf32(kv.w);
            *reinterpret_cast<float4*>(&Ks[r * KPITCH + dv * 4]) = kv;
            float4 vv = *reinterpret_cast<const float4*>(vbase + (size_t)(s0 + r) * NQKV + dv * 4);
            vv.x = to_tf32(vv.x); vv.y = to_tf32(vv.y); vv.z = to_tf32(vv.z); vv.w = to_tf32(vv.w);
            *reinterpret_cast<float4*>(&Vs[r * VPITCH + dv * 4]) = vv;
        }
        __syncthreads();

        // ---- S = Q @ K^T : 8 n-tiles of 8 keys ----
        float sacc[8][4];
#pragma unroll
        for (int j = 0; j < 8; j++) { sacc[j][0]=0.f; sacc[j][1]=0.f; sacc[j][2]=0.f; sacc[j][3]=0.f; }
#pragma unroll
        for (int j = 0; j < 8; j++) {
            const float* kb_ptr = &Ks[(j * 8 + g) * KPITCH + t4];
#pragma unroll
            for (int s = 0; s < 16; s++) {
                uint32_t bf[2];
                bf[0] = __float_as_uint(kb_ptr[s * 8]);
                bf[1] = __float_as_uint(kb_ptr[s * 8 + 4]);
                mma_tf32(sacc[j], qf[s], bf);
            }
        }

        // ---- causal mask (diagonal block only) ----
        if (kb == nkb - 1) {
            const int lr0 = warp * 16 + g;       // local row within 64
            const int lr1 = lr0 + 8;
#pragma unroll
            for (int j = 0; j < 8; j++) {
                int c = j * 8 + 2 * t4;
                if (c     > lr0) sacc[j][0] = -1e30f;
                if (c + 1 > lr0) sacc[j][1] = -1e30f;
                if (c     > lr1) sacc[j][2] = -1e30f;
                if (c + 1 > lr1) sacc[j][3] = -1e30f;
            }
        }

        // ---- online softmax in registers ----
        {
            float mx0 = -1e30f, mx1 = -1e30f;
#pragma unroll
            for (int j = 0; j < 8; j++) {
                mx0 = fmaxf(mx0, fmaxf(sacc[j][0], sacc[j][1]));
                mx1 = fmaxf(mx1, fmaxf(sacc[j][2], sacc[j][3]));
            }
            mx0 = fmaxf(mx0, __shfl_xor_sync(0xffffffffu, mx0, 1));
            mx0 = fmaxf(mx0, __shfl_xor_sync(0xffffffffu, mx0, 2));
            mx1 = fmaxf(mx1, __shfl_xor_sync(0xffffffffu, mx1, 1));
            mx1 = fmaxf(mx1, __shfl_xor_sync(0xffffffffu, mx1, 2));
            float mn0 = fmaxf(m0r, mx0), mn1 = fmaxf(m1r, mx1);
            float co0 = __expf(m0r - mn0), co1 = __expf(m1r - mn1);
            m0r = mn0; m1r = mn1;
            float s0sum = 0.f, s1sum = 0.f;
#pragma unroll
            for (int j = 0; j < 8; j++) {
                sacc[j][0] = __expf(sacc[j][0] - mn0);
                sacc[j][1] = __expf(sacc[j][1] - mn0);
                sacc[j][2] = __expf(sacc[j][2] - mn1);
                sacc[j][3] = __expf(sacc[j][3] - mn1);
                s0sum += sacc[j][0] + sacc[j][1];
                s1sum += sacc[j][2] + sacc[j][3];
            }
            s0sum += __shfl_xor_sync(0xffffffffu, s0sum, 1);
            s0sum += __shfl_xor_sync(0xffffffffu, s0sum, 2);
            s1sum += __shfl_xor_sync(0xffffffffu, s1sum, 1);
            s1sum += __shfl_xor_sync(0xffffffffu, s1sum, 2);
            l0r = l0r * co0 + s0sum;
            l1r = l1r * co1 + s1sum;
            // rescale O
#pragma unroll
            for (int n = 0; n < 16; n++) {
                o[n][0] *= co0; o[n][1] *= co0;
                o[n][2] *= co1; o[n][3] *= co1;
            }
        }

        // ---- P -> smem (per-warp private rows), tf32 ----
#pragma unroll
        for (int j = 0; j < 8; j++) {
            float2 p0 = make_float2(to_tf32(sacc[j][0]), to_tf32(sacc[j][1]));
            float2 p1 = make_float2(to_tf32(sacc[j][2]), to_tf32(sacc[j][3]));
            *reinterpret_cast<float2*>(&Ps[r0 * PPITCH + j * 8 + 2 * t4]) = p0;
            *reinterpret_cast<float2*>(&Ps[r1 * PPITCH + j * 8 + 2 * t4]) = p1;
        }
        __syncwarp();

        // ---- O += P @ V : 16 n-tiles of 8 dims ----
#pragma unroll
        for (int s = 0; s < 8; s++) {
            uint32_t af[4];
            af[0] = __float_as_uint(Ps[r0 * PPITCH + s * 8 + t4]);
            af[1] = __float_as_uint(Ps[r1 * PPITCH + s * 8 + t4]);
            af[2] = __float_as_uint(Ps[r0 * PPITCH + s * 8 + t4 + 4]);
            af[3] = __float_as_uint(Ps[r1 * PPITCH + s * 8 + t4 + 4]);
            const float* vb0 = &Vs[(s * 8 + t4) * VPITCH + g];
            const float* vb1 = &Vs[(s * 8 + t4 + 4) * VPITCH + g];
#pragma unroll
            for (int n = 0; n < 16; n++) {
                uint32_t bf[2];
                bf[0] = __float_as_uint(vb0[n * 8]);
                bf[1] = __float_as_uint(vb1[n * 8]);
                mma_tf32(o[n], af, bf);
            }
        }
        __syncwarp();
    }

    // epilogue: normalize, write [B,T,NQ,D]
    {
        float rl0 = 1.0f / l0r, rl1 = 1.0f / l1r;
        int qr0 = q0 + r0, qr1 = q0 + r1;
        float* op0 = out + ((size_t)(b * TT + qr0) * NQ + h) * DD;
        float* op1 = out + ((size_t)(b * TT + qr1) * NQ + h) * DD;
#pragma unroll
        for (int n = 0; n < 16; n++) {
            *reinterpret_cast<float2*>(op0 + n * 8 + 2 * t4) =
                make_float2(o[n][0] * rl0, o[n][1] * rl0);
            *reinterpret_cast<float2*>(op1 + n * 8 + 2 * t4) =
                make_float2(o[n][2] * rl1, o[n][3] * rl1);
        }
    }
}

// ---------------- launch ----------------
extern "C" void kernel_launch(void* const* d_in, const int* in_sizes, int n_in,
                              void* d_out, int out_size) {
    const float* x  = (const float*)d_in[0];
    const float* Wk = (const float*)d_in[1];
    const float* Wv = (const float*)d_in[2];
    const float* Wq = (const float*)d_in[3];
    const float* Wp = (const float*)d_in[4];
    const float* bp = (const float*)d_in[5];
    float* out = (float*)d_out;

    float *wcat, *wpT, *qkv, *attn;
    cudaGetSymbolAddress((void**)&wcat, g_Wcat);
    cudaGetSymbolAddress((void**)&wpT,  g_WpT);
    cudaGetSymbolAddress((void**)&qkv,  g_qkv);
    cudaGetSymbolAddress((void**)&attn, g_attn);

    cudaFuncSetAttribute(mqa_fa_kernel, cudaFuncAttributeMaxDynamicSharedMemorySize, FASMEM);

    // 1) transpose+pack weights to K-major (tf32-rounded)
    pack_qkv_t_kernel<<<dim3(CC / 32, NQKV / 32), dim3(32, 8)>>>(Wk, Wv, Wq, wcat);
    pack_wp_t_kernel<<<dim3(CC / 32, CC / 32), dim3(32, 8)>>>(Wp, wpT);

    // 2) fused QKV projection (wmma tf32)
    wmma_gemm<<<dim3(NQKV / 128, MM / 128), 256>>>(x, wcat, nullptr, qkv, MM, NQKV, CC);

    // 3) causal MQA attention (mma.sync tf32, register-resident) -> [B,T,NQ,D]
    mqa_fa_kernel<<<dim3(TT / 64, NQ, BB), 128, FASMEM>>>(qkv, attn);

    // 4) output projection (wmma tf32) + bias
    wmma_gemm<<<dim3(CC / 128, MM / 128), 256>>>(attn, wpT, bp, out, MM, CC, CC);
}

// round 6
// speedup vs baseline: 3.7163x; 1.3394x over previous
#include <cuda_runtime.h>
#include <cuda_bf16.h>
#include <cstdint>
#include <math.h>

// Problem constants
#define BB   4
#define TT   2048
#define CC   1024
#define NQ   8
#define DD   128
#define MM   (BB*TT)          // 8192 rows
#define NQKV (DD*(NQ+2))      // 1280

// ---------------- scratch (no allocations allowed) ----------------
__device__ float g_Wcat[NQKV * CC];     // [1280][1024] K-major (transposed, tf32-rounded)
__device__ float g_WpT [CC * CC];       // [1024][1024] K-major (transposed, tf32-rounded)
__device__ float g_xr  [MM * CC];       // [8192][1024]  x, tf32-rounded
__device__ float g_qkv [MM * NQKV];     // [8192][1280]  k|v|q per token
__device__ float g_attn[MM * CC];       // [8192][1024]  attention out (tf32-rounded)

__device__ __forceinline__ float to_tf32(float x) {
    float r;
    asm("cvt.rna.tf32.f32 %0, %1;" : "=f"(r) : "f"(x));
    return r;
}
__device__ __forceinline__ uint32_t smem_u32(const void* p) {
    uint32_t a;
    asm("{ .reg .u64 t; cvta.to.shared.u64 t, %1; cvt.u32.u64 %0, t; }" : "=r"(a) : "l"(p));
    return a;
}

// mma.sync m16n8k8 tf32: C[16x8] += A[16x8] * B[8x8]
__device__ __forceinline__ void mma_tf32(float c[4], const uint32_t a[4], const uint32_t b[2]) {
    asm volatile(
        "mma.sync.aligned.m16n8k8.row.col.f32.tf32.tf32.f32 "
        "{%0,%1,%2,%3}, {%4,%5,%6,%7}, {%8,%9}, {%0,%1,%2,%3};"
        : "+f"(c[0]), "+f"(c[1]), "+f"(c[2]), "+f"(c[3])
        : "r"(a[0]), "r"(a[1]), "r"(a[2]), "r"(a[3]), "r"(b[0]), "r"(b[1]));
}

#define CP_ASYNC16(smaddr, gptr) \
    asm volatile("cp.async.cg.shared.global [%0], [%1], 16;" :: "r"(smaddr), "l"(gptr))
#define CP_COMMIT() asm volatile("cp.async.commit_group;")
#define CP_WAIT1()  asm volatile("cp.async.wait_group 1;")

// ---------------- input rounding ----------------
__global__ void round_x_kernel(const float* __restrict__ x, float* __restrict__ out, int n4) {
    int i = blockIdx.x * 256 + threadIdx.x;
    if (i >= n4) return;
    float4 v = reinterpret_cast<const float4*>(x)[i];
    v.x = to_tf32(v.x); v.y = to_tf32(v.y); v.z = to_tf32(v.z); v.w = to_tf32(v.w);
    reinterpret_cast<float4*>(out)[i] = v;
}

// ---------------- weight transposes (to K-major [N][K], tf32-rounded) ----------------
__global__ void pack_qkv_t_kernel(const float* __restrict__ Wk,
                                  const float* __restrict__ Wv,
                                  const float* __restrict__ Wq,
                                  float* __restrict__ out) {
    __shared__ float t[32][33];
    int c0 = blockIdx.x * 32;
    int n0 = blockIdx.y * 32;
    int tx = threadIdx.x, ty = threadIdx.y;
#pragma unroll
    for (int p = 0; p < 4; p++) {
        int c = c0 + ty + p * 8;
        int n = n0 + tx;
        float v;
        if (n < DD)            v = Wk[c * DD + n];
        else if (n < 2 * DD)   v = Wv[c * DD + (n - DD)];
        else {
            int h = (n - 2 * DD) >> 7;
            int d = (n - 2 * DD) & 127;
            v = Wq[((size_t)h * CC + c) * DD + d];
        }
        t[ty + p * 8][tx] = to_tf32(v);
    }
    __syncthreads();
#pragma unroll
    for (int p = 0; p < 4; p++)
        out[(size_t)(n0 + ty + p * 8) * CC + c0 + tx] = t[tx][ty + p * 8];
}

__global__ void pack_wp_t_kernel(const float* __restrict__ Wp, float* __restrict__ out) {
    __shared__ float t[32][33];
    int c0 = blockIdx.x * 32;
    int n0 = blockIdx.y * 32;
    int tx = threadIdx.x, ty = threadIdx.y;
#pragma unroll
    for (int p = 0; p < 4; p++)
        t[ty + p * 8][tx] = to_tf32(Wp[(size_t)(c0 + ty + p * 8) * CC + n0 + tx]);
    __syncthreads();
#pragma unroll
    for (int p = 0; p < 4; p++)
        out[(size_t)(n0 + ty + p * 8) * CC + c0 + tx] = t[tx][ty + p * 8];
}

// ---------------- mma.sync tf32 GEMM with cp.async pipeline ----------------
// C[M,N] = A[M,K] @ Bt[N,K]^T (+bias). A, Bt pre-rounded to tf32.
// 256 threads / 8 warps (4m x 2n), CTA 128x128, warp 32x64, K-chunk 16, 3 stages.
#define GP     20                 // smem row pitch (floats) — conflict-free for frag pattern
#define STG_F  (128 * GP)         // floats per tile per stage
#define B_OFF  (3 * STG_F)        // B region offset (floats)
#define GEMM_SMEM (6 * STG_F * 4) // bytes

__device__ __forceinline__ void gemm_issue(uint32_t smb, int stage,
                                           const float* __restrict__ Ab,
                                           const float* __restrict__ Bb,
                                           int K, int kc, int tid) {
    int row = tid >> 1;
    int cq  = (tid & 1) * 8;
    uint32_t a_s = smb + (uint32_t)(stage * STG_F + row * GP + cq) * 4;
    const float* a_g = Ab + (size_t)row * K + kc * 16 + cq;
    CP_ASYNC16(a_s, a_g);
    CP_ASYNC16(a_s + 16, a_g + 4);
    uint32_t b_s = smb + (uint32_t)(B_OFF + stage * STG_F + row * GP + cq) * 4;
    const float* b_g = Bb + (size_t)row * K + kc * 16 + cq;
    CP_ASYNC16(b_s, b_g);
    CP_ASYNC16(b_s + 16, b_g + 4);
}

__global__ __launch_bounds__(256, 2)
void mma_gemm(const float* __restrict__ A, const float* __restrict__ Bt,
              const float* __restrict__ bias, float* __restrict__ C,
              int M, int N, int K) {
    extern __shared__ float sm[];
    const uint32_t smb = smem_u32(sm);

    const int tid  = threadIdx.x;
    const int warp = tid >> 5;
    const int lane = tid & 31;
    const int g    = lane >> 2;
    const int t4   = lane & 3;
    const int wm   = warp >> 1;       // 0..3
    const int wn   = warp & 1;        // 0..1
    const int m0 = blockIdx.y * 128;
    const int n0 = blockIdx.x * 128;

    const float* Ab = A  + (size_t)m0 * K;
    const float* Bb = Bt + (size_t)n0 * K;
    const int nk = K / 16;

    float acc[2][8][4];
#pragma unroll
    for (int i = 0; i < 2; i++)
#pragma unroll
        for (int j = 0; j < 8; j++) { acc[i][j][0]=0.f; acc[i][j][1]=0.f; acc[i][j][2]=0.f; acc[i][j][3]=0.f; }

    // prologue: stages 0,1
    gemm_issue(smb, 0, Ab, Bb, K, 0, tid); CP_COMMIT();
    gemm_issue(smb, 1, Ab, Bb, K, 1, tid); CP_COMMIT();

    const int arow0 = (wm * 32 + g) * GP;            // m-tile 0 row base
    const int brow0 = (wn * 64 + g) * GP;            // n-tile base

    for (int c = 0; c < nk; c++) {
        const int stage = c % 3;
        CP_WAIT1();
        __syncthreads();

        if (c + 2 < nk) {
            gemm_issue(smb, (c + 2) % 3, Ab, Bb, K, c + 2, tid);
        }
        CP_COMMIT();

        const float* Abuf = sm + stage * STG_F;
        const float* Bbuf = sm + B_OFF + stage * STG_F;

#pragma unroll
        for (int ks = 0; ks < 2; ks++) {
            uint32_t af[2][4];
#pragma unroll
            for (int mt = 0; mt < 2; mt++) {
                const float* ap = Abuf + arow0 + mt * 16 * GP + ks * 8 + t4;
                af[mt][0] = __float_as_uint(ap[0]);
                af[mt][1] = __float_as_uint(ap[8 * GP]);
                af[mt][2] = __float_as_uint(ap[4]);
                af[mt][3] = __float_as_uint(ap[8 * GP + 4]);
            }
#pragma unroll
            for (int j = 0; j < 8; j++) {
                const float* bp = Bbuf + brow0 + j * 8 * GP + ks * 8 + t4;
                uint32_t bf[2];
                bf[0] = __float_as_uint(bp[0]);
                bf[1] = __float_as_uint(bp[4]);
                mma_tf32(acc[0][j], af[0], bf);
                mma_tf32(acc[1][j], af[1], bf);
            }
        }
        __syncthreads();
    }

    // epilogue: direct float2 stores + bias
#pragma unroll
    for (int j = 0; j < 8; j++) {
        int gn = n0 + wn * 64 + j * 8 + 2 * t4;
        float2 bv = make_float2(0.f, 0.f);
        if (bias) bv = *reinterpret_cast<const float2*>(bias + gn);
#pragma unroll
        for (int mt = 0; mt < 2; mt++) {
            int gm = m0 + wm * 32 + mt * 16 + g;
            *reinterpret_cast<float2*>(C + (size_t)gm * N + gn) =
                make_float2(acc[mt][j][0] + bv.x, acc[mt][j][1] + bv.y);
            *reinterpret_cast<float2*>(C + (size_t)(gm + 8) * N + gn) =
                make_float2(acc[mt][j][2] + bv.x, acc[mt][j][3] + bv.y);
        }
    }
}

// ---------------- causal MQA flash attention, mma.sync tf32 (validated R5) ----------------
#define KPITCH 132
#define VPITCH 136
#define PPITCH 68
#define FASMEM ((64*KPITCH + 64*KPITCH + 64*VPITCH) * 4)

__global__ __launch_bounds__(128, 2)
void mqa_fa_kernel(const float* __restrict__ qkv, float* __restrict__ out) {
    extern __shared__ float smf[];
    float* Qs = smf;
    float* Ks = Qs + 64 * KPITCH;
    float* Vs = Ks + 64 * KPITCH;
    float* Ps = Qs;

    const int tid  = threadIdx.x;
    const int warp = tid >> 5;
    const int lane = tid & 31;
    const int g    = lane >> 2;
    const int t4   = lane & 3;
    const int qt = gridDim.x - 1 - blockIdx.x;
    const int h  = blockIdx.y;
    const int b  = blockIdx.z;
    const int q0 = qt * 64;
    const float scale = 1.0f / 32.0f;

    const float* kbase = qkv + (size_t)(b * TT) * NQKV;
    const float* vbase = kbase + DD;
    const float* qbase = kbase + 2 * DD + h * DD;

    for (int l = tid; l < 64 * 32; l += 128) {
        int r  = l >> 5;
        int dv = l & 31;
        float4 v = *reinterpret_cast<const float4*>(qbase + (size_t)(q0 + r) * NQKV + dv * 4);
        v.x = to_tf32(v.x * scale); v.y = to_tf32(v.y * scale);
        v.z = to_tf32(v.z * scale); v.w = to_tf32(v.w * scale);
        *reinterpret_cast<float4*>(&Qs[r * KPITCH + dv * 4]) = v;
    }
    __syncthreads();

    const int r0 = warp * 16 + g;
    const int r1 = r0 + 8;
    uint32_t qf[16][4];
#pragma unroll
    for (int s = 0; s < 16; s++) {
        qf[s][0] = __float_as_uint(Qs[r0 * KPITCH + s * 8 + t4]);
        qf[s][1] = __float_as_uint(Qs[r1 * KPITCH + s * 8 + t4]);
        qf[s][2] = __float_as_uint(Qs[r0 * KPITCH + s * 8 + t4 + 4]);
        qf[s][3] = __float_as_uint(Qs[r1 * KPITCH + s * 8 + t4 + 4]);
    }

    float o[16][4];
#pragma unroll
    for (int n = 0; n < 16; n++) { o[n][0]=0.f; o[n][1]=0.f; o[n][2]=0.f; o[n][3]=0.f; }
    float m0r = -1e30f, m1r = -1e30f, l0r = 0.f, l1r = 0.f;

    const int nkb = qt + 1;
    for (int kb = 0; kb < nkb; kb++) {
        const int s0 = kb * 64;
        __syncthreads();

        for (int l = tid; l < 64 * 32; l += 128) {
            int r  = l >> 5;
            int dv = l & 31;
            float4 kv = *reinterpret_cast<const float4*>(kbase + (size_t)(s0 + r) * NQKV + dv * 4);
            kv.x = to_tf32(kv.x); kv.y = to_tf32(kv.y); kv.z = to_tf32(kv.z); kv.w = to_tf32(kv.w);
            *reinterpret_cast<float4*>(&Ks[r * KPITCH + dv * 4]) = kv;
            float4 vv = *reinterpret_cast<const float4*>(vbase + (size_t)(s0 + r) * NQKV + dv * 4);
            vv.x = to_tf32(vv.x); vv.y = to_tf32(vv.y); vv.z = to_tf32(vv.z); vv.w = to_tf32(vv.w);
            *reinterpret_cast<float4*>(&Vs[r * VPITCH + dv * 4]) = vv;
        }
        __syncthreads();

        float sacc[8][4];
#pragma unroll
        for (int j = 0; j < 8; j++) { sacc[j][0]=0.f; sacc[j][1]=0.f; sacc[j][2]=0.f; sacc[j][3]=0.f; }
#pragma unroll
        for (int j = 0; j < 8; j++) {
            const float* kb_ptr = &Ks[(j * 8 + g) * KPITCH + t4];
#pragma unroll
            for (int s = 0; s < 16; s++) {
                uint32_t bf[2];
                bf[0] = __float_as_uint(kb_ptr[s * 8]);
                bf[1] = __float_as_uint(kb_ptr[s * 8 + 4]);
                mma_tf32(sacc[j], qf[s], bf);
            }
        }

        if (kb == nkb - 1) {
            const int lr0 = warp * 16 + g;
            const int lr1 = lr0 + 8;
#pragma unroll
            for (int j = 0; j < 8; j++) {
                int c = j * 8 + 2 * t4;
                if (c     > lr0) sacc[j][0] = -1e30f;
                if (c + 1 > lr0) sacc[j][1] = -1e30f;
                if (c     > lr1) sacc[j][2] = -1e30f;
                if (c + 1 > lr1) sacc[j][3] = -1e30f;
            }
        }

        {
            float mx0 = -1e30f, mx1 = -1e30f;
#pragma unroll
            for (int j = 0; j < 8; j++) {
                mx0 = fmaxf(mx0, fmaxf(sacc[j][0], sacc[j][1]));
                mx1 = fmaxf(mx1, fmaxf(sacc[j][2], sacc[j][3]));
            }
            mx0 = fmaxf(mx0, __shfl_xor_sync(0xffffffffu, mx0, 1));
            mx0 = fmaxf(mx0, __shfl_xor_sync(0xffffffffu, mx0, 2));
            mx1 = fmaxf(mx1, __shfl_xor_sync(0xffffffffu, mx1, 1));
            mx1 = fmaxf(mx1, __shfl_xor_sync(0xffffffffu, mx1, 2));
            float mn0 = fmaxf(m0r, mx0), mn1 = fmaxf(m1r, mx1);
            float co0 = __expf(m0r - mn0), co1 = __expf(m1r - mn1);
            m0r = mn0; m1r = mn1;
            float s0sum = 0.f, s1sum = 0.f;
#pragma unroll
            for (int j = 0; j < 8; j++) {
                sacc[j][0] = __expf(sacc[j][0] - mn0);
                sacc[j][1] = __expf(sacc[j][1] - mn0);
                sacc[j][2] = __expf(sacc[j][2] - mn1);
                sacc[j][3] = __expf(sacc[j][3] - mn1);
                s0sum += sacc[j][0] + sacc[j][1];
                s1sum += sacc[j][2] + sacc[j][3];
            }
            s0sum += __shfl_xor_sync(0xffffffffu, s0sum, 1);
            s0sum += __shfl_xor_sync(0xffffffffu, s0sum, 2);
            s1sum += __shfl_xor_sync(0xffffffffu, s1sum, 1);
            s1sum += __shfl_xor_sync(0xffffffffu, s1sum, 2);
            l0r = l0r * co0 + s0sum;
            l1r = l1r * co1 + s1sum;
#pragma unroll
            for (int n = 0; n < 16; n++) {
                o[n][0] *= co0; o[n][1] *= co0;
                o[n][2] *= co1; o[n][3] *= co1;
            }
        }

#pragma unroll
        for (int j = 0; j < 8; j++) {
            float2 p0 = make_float2(to_tf32(sacc[j][0]), to_tf32(sacc[j][1]));
            float2 p1 = make_float2(to_tf32(sacc[j][2]), to_tf32(sacc[j][3]));
            *reinterpret_cast<float2*>(&Ps[r0 * PPITCH + j * 8 + 2 * t4]) = p0;
            *reinterpret_cast<float2*>(&Ps[r1 * PPITCH + j * 8 + 2 * t4]) = p1;
        }
        __syncwarp();

#pragma unroll
        for (int s = 0; s < 8; s++) {
            uint32_t af[4];
            af[0] = __float_as_uint(Ps[r0 * PPITCH + s * 8 + t4]);
            af[1] = __float_as_uint(Ps[r1 * PPITCH + s * 8 + t4]);
            af[2] = __float_as_uint(Ps[r0 * PPITCH + s * 8 + t4 + 4]);
            af[3] = __float_as_uint(Ps[r1 * PPITCH + s * 8 + t4 + 4]);
            const float* vb0 = &Vs[(s * 8 + t4) * VPITCH + g];
            const float* vb1 = &Vs[(s * 8 + t4 + 4) * VPITCH + g];
#pragma unroll
            for (int n = 0; n < 16; n++) {
                uint32_t bf[2];
                bf[0] = __float_as_uint(vb0[n * 8]);
                bf[1] = __float_as_uint(vb1[n * 8]);
                mma_tf32(o[n], af, bf);
            }
        }
        __syncwarp();
    }

    // epilogue: normalize, tf32-round (GEMM2 A-side rounding), write [B,T,NQ,D]
    {
        float rl0 = 1.0f / l0r, rl1 = 1.0f / l1r;
        int qr0 = q0 + r0, qr1 = q0 + r1;
        float* op0 = out + ((size_t)(b * TT + qr0) * NQ + h) * DD;
        float* op1 = out + ((size_t)(b * TT + qr1) * NQ + h) * DD;
#pragma unroll
        for (int n = 0; n < 16; n++) {
            *reinterpret_cast<float2*>(op0 + n * 8 + 2 * t4) =
                make_float2(to_tf32(o[n][0] * rl0), to_tf32(o[n][1] * rl0));
            *reinterpret_cast<float2*>(op1 + n * 8 + 2 * t4) =
                make_float2(to_tf32(o[n][2] * rl1), to_tf32(o[n][3] * rl1));
        }
    }
}

// ---------------- launch ----------------
extern "C" void kernel_launch(void* const* d_in, const int* in_sizes, int n_in,
                              void* d_out, int out_size) {
    const float* x  = (const float*)d_in[0];
    const float* Wk = (const float*)d_in[1];
    const float* Wv = (const float*)d_in[2];
    const float* Wq = (const float*)d_in[3];
    const float* Wp = (const float*)d_in[4];
    const float* bp = (const float*)d_in[5];
    float* out = (float*)d_out;

    float *wcat, *wpT, *xr, *qkv, *attn;
    cudaGetSymbolAddress((void**)&wcat, g_Wcat);
    cudaGetSymbolAddress((void**)&wpT,  g_WpT);
    cudaGetSymbolAddress((void**)&xr,   g_xr);
    cudaGetSymbolAddress((void**)&qkv,  g_qkv);
    cudaGetSymbolAddress((void**)&attn, g_attn);

    cudaFuncSetAttribute(mma_gemm, cudaFuncAttributeMaxDynamicSharedMemorySize, GEMM_SMEM);
    cudaFuncSetAttribute(mqa_fa_kernel, cudaFuncAttributeMaxDynamicSharedMemorySize, FASMEM);

    // 1) round x; transpose+pack weights to K-major (all tf32-rounded)
    round_x_kernel<<<(MM * CC / 4 + 255) / 256, 256>>>(x, xr, MM * CC / 4);
    pack_qkv_t_kernel<<<dim3(CC / 32, NQKV / 32), dim3(32, 8)>>>(Wk, Wv, Wq, wcat);
    pack_wp_t_kernel<<<dim3(CC / 32, CC / 32), dim3(32, 8)>>>(Wp, wpT);

    // 2) fused QKV projection (mma.sync tf32 + cp.async)
    mma_gemm<<<dim3(NQKV / 128, MM / 128), 256, GEMM_SMEM>>>(xr, wcat, nullptr, qkv, MM, NQKV, CC);

    // 3) causal MQA attention (mma.sync tf32) -> [B,T,NQ,D], tf32-rounded
    mqa_fa_kernel<<<dim3(TT / 64, NQ, BB), 128, FASMEM>>>(qkv, attn);

    // 4) output projection (mma.sync tf32 + cp.async) + bias
    mma_gemm<<<dim3(CC / 128, MM / 128), 256, GEMM_SMEM>>>(attn, wpT, bp, out, MM, CC, CC);
}